// round 3
// baseline (speedup 1.0000x reference)
#include <cuda_runtime.h>
#include <math.h>

#define NN 50000
#define NE 800000

__device__ float g_h [NN*64];
__device__ float g_p0[NN*64];
__device__ float g_q0[NN*64];
__device__ float g_p1[NN*64];
__device__ float g_q1[NN*64];
__device__ float g_ft [NN*64];
__device__ float g_ft2[NN*64];
__device__ float g_h3[(size_t)NE*64];
__device__ float g_s [NE*2];
__device__ int   g_count [NN];
__device__ int   g_off   [NN];
__device__ int   g_cursor[NN];
__device__ int   g_perm  [NE];

__device__ __forceinline__ float ftanh(float x){
    float e = __expf(2.0f*x);
    return 1.0f - __fdividef(2.0f, e + 1.0f);
}
__device__ __forceinline__ float fsigm(float x){
    return __fdividef(1.0f, 1.0f + __expf(-x));
}

#define KK_COMP(v,kk) ((kk)==0?(v).x:((kk)==1?(v).y:((kk)==2?(v).z:(v).w)))
#define ROW_FMA8(ar, va) do{ \
  ar[0] += (va)*w0.x; ar[1] += (va)*w0.y; ar[2] += (va)*w0.z; ar[3] += (va)*w0.w; \
  ar[4] += (va)*w1.x; ar[5] += (va)*w1.y; ar[6] += (va)*w1.z; ar[7] += (va)*w1.w; }while(0)

__device__ __forceinline__ void gemm4x8(const float (*A)[68], const float (*W)[68],
                                        int er, int c0, float acc[4][8]){
  #pragma unroll
  for (int k = 0; k < 64; k += 4){
    float4 a0 = *(const float4*)&A[er+0][k];
    float4 a1 = *(const float4*)&A[er+1][k];
    float4 a2 = *(const float4*)&A[er+2][k];
    float4 a3 = *(const float4*)&A[er+3][k];
    #pragma unroll
    for (int kk = 0; kk < 4; kk++){
      float4 w0 = *(const float4*)&W[k+kk][c0];
      float4 w1 = *(const float4*)&W[k+kk][c0+4];
      float va0 = KK_COMP(a0,kk), va1 = KK_COMP(a1,kk);
      float va2 = KK_COMP(a2,kk), va3 = KK_COMP(a3,kk);
      ROW_FMA8(acc[0], va0); ROW_FMA8(acc[1], va1);
      ROW_FMA8(acc[2], va2); ROW_FMA8(acc[3], va3);
    }
  }
}

__device__ __forceinline__ void gemm2x8(const float (*A)[68], const float (*W)[68],
                                        int rr, int c0, float acc[2][8]){
  #pragma unroll
  for (int k = 0; k < 64; k += 4){
    float4 a0 = *(const float4*)&A[rr+0][k];
    float4 a1 = *(const float4*)&A[rr+1][k];
    #pragma unroll
    for (int kk = 0; kk < 4; kk++){
      float4 w0 = *(const float4*)&W[k+kk][c0];
      float4 w1 = *(const float4*)&W[k+kk][c0+4];
      float va0 = KK_COMP(a0,kk), va1 = KK_COMP(a1,kk);
      ROW_FMA8(acc[0], va0); ROW_FMA8(acc[1], va1);
    }
  }
}

__global__ void k_zero(){
  int i = blockIdx.x*256 + threadIdx.x;
  if (i < NN) g_count[i] = 0;
}

__global__ void __launch_bounds__(256) k_node_h(const float* __restrict__ x,
                                                const float* __restrict__ W,
                                                const float* __restrict__ b){
  __shared__ float Xs[64][68];
  __shared__ float Ws[64][68];
  int t = threadIdx.x;
  int r0 = blockIdx.x * 64;
  #pragma unroll
  for (int j = 0; j < 4; j++){
    int idx = t + 256*j;
    int r = idx >> 4, c4 = (idx & 15) * 4;
    float4 v = make_float4(0.f,0.f,0.f,0.f);
    if (r0 + r < NN) v = *(const float4*)&x[(size_t)(r0+r)*64 + c4];
    *(float4*)&Xs[r][c4] = v;
    *(float4*)&Ws[r][c4] = *(const float4*)&W[r*64 + c4];
  }
  __syncthreads();
  int cg = t & 7, eg = t >> 3;
  int c0 = cg * 8, rr = eg * 2;
  float acc[2][8] = {};
  gemm2x8(Xs, Ws, rr, c0, acc);
  float bv[8];
  *(float4*)&bv[0] = *(const float4*)&b[c0];
  *(float4*)&bv[4] = *(const float4*)&b[c0+4];
  #pragma unroll
  for (int i = 0; i < 2; i++){
    int r = r0 + rr + i;
    if (r < NN){
      float o[8];
      #pragma unroll
      for (int j = 0; j < 8; j++) o[j] = acc[i][j] + bv[j];
      *(float4*)&g_h[(size_t)r*64 + c0]   = *(float4*)&o[0];
      *(float4*)&g_h[(size_t)r*64 + c0+4] = *(float4*)&o[4];
    }
  }
}

__global__ void __launch_bounds__(256) k_node_pq(const float* __restrict__ Wx0, const float* __restrict__ Wh0, const float* __restrict__ b0,
                                                 const float* __restrict__ Wx1, const float* __restrict__ Wh1, const float* __restrict__ b1){
  extern __shared__ float sm[];
  float (*Hs)[68] = (float(*)[68])sm;
  float (*Ts)[68] = (float(*)[68])(sm + 64*68);
  float (*Ws)[68] = (float(*)[68])(sm + 2*64*68);
  int t = threadIdx.x;
  int r0 = blockIdx.x * 64;
  #pragma unroll
  for (int j = 0; j < 4; j++){
    int idx = t + 256*j;
    int r = idx >> 4, c4 = (idx & 15) * 4;
    float4 v = make_float4(0.f,0.f,0.f,0.f);
    if (r0 + r < NN) v = *(const float4*)&g_h[(size_t)(r0+r)*64 + c4];
    *(float4*)&Hs[r][c4] = v;
  }
  int cg = t & 7, eg = t >> 3;
  int c0 = cg * 8, rr = eg * 2;

  for (int enc = 0; enc < 2; enc++){
    const float* Wx = enc ? Wx1 : Wx0;
    const float* Wh = enc ? Wh1 : Wh0;
    const float* bb = enc ? b1  : b0;
    float* gp = enc ? g_p1 : g_p0;
    float* gq = enc ? g_q1 : g_q0;
    __syncthreads();
    #pragma unroll
    for (int j = 0; j < 4; j++){
      int idx = t + 256*j;
      int r = idx >> 4, c4 = (idx & 15) * 4;
      *(float4*)&Ws[r][c4] = *(const float4*)&Wx[r*64 + c4];
    }
    __syncthreads();
    float acc[2][8] = {};
    gemm2x8(Hs, Ws, rr, c0, acc);
    float bv[8];
    *(float4*)&bv[0] = *(const float4*)&bb[c0];
    *(float4*)&bv[4] = *(const float4*)&bb[c0+4];
    #pragma unroll
    for (int i = 0; i < 2; i++){
      int r = r0 + rr + i;
      if (r < NN){
        *(float4*)&gp[(size_t)r*64 + c0]   = *(float4*)&acc[i][0];
        *(float4*)&gp[(size_t)r*64 + c0+4] = *(float4*)&acc[i][4];
      }
      #pragma unroll
      for (int j = 0; j < 8; j++) Ts[rr+i][c0+j] = ftanh(acc[i][j] + bv[j]);
    }
    __syncthreads();
    #pragma unroll
    for (int j = 0; j < 4; j++){
      int idx = t + 256*j;
      int r = idx >> 4, c4 = (idx & 15) * 4;
      *(float4*)&Ws[r][c4] = *(const float4*)&Wh[r*64 + c4];
    }
    __syncthreads();
    float acc2[2][8] = {};
    gemm2x8(Ts, Ws, rr, c0, acc2);
    #pragma unroll
    for (int i = 0; i < 2; i++){
      int r = r0 + rr + i;
      if (r < NN){
        *(float4*)&gq[(size_t)r*64 + c0]   = *(float4*)&acc2[i][0];
        *(float4*)&gq[(size_t)r*64 + c0+4] = *(float4*)&acc2[i][4];
      }
    }
  }
}

__global__ void __launch_bounds__(256) k_edge1(
    const float* __restrict__ ef0, const float* __restrict__ ef1,
    const int* __restrict__ src, const int* __restrict__ dst,
    const float* __restrict__ Wx0, const float* __restrict__ Wh0, const float* __restrict__ b0,
    const float* __restrict__ Wx1, const float* __restrict__ Wh1, const float* __restrict__ b1,
    const float* __restrict__ attn0, const float* __restrict__ eta0,
    const float* __restrict__ attn1, const float* __restrict__ eta1,
    const float* __restrict__ delta)
{
  extern __shared__ float sm[];
  float (*As)[68] = (float(*)[68])sm;
  float (*Ws)[68] = (float(*)[68])(sm + 128*68);
  int* s_src = (int*)(sm + 128*68 + 64*68);
  int* s_dst = s_src + 128;

  int t = threadIdx.x;
  int ebase = blockIdx.x * 128;
  if (t < 128) s_src[t] = src[ebase + t];
  else         s_dst[t-128] = dst[ebase + t - 128];

  int cg = t & 7, eg = t >> 3;
  int c0 = cg * 8;
  int er = eg * 4;
  int head = cg >> 2;
  float edot[2][4];

  for (int enc = 0; enc < 2; enc++){
    const float* ef  = enc ? ef1  : ef0;
    const float* Wx  = enc ? Wx1  : Wx0;
    const float* Wh  = enc ? Wh1  : Wh0;
    const float* bb  = enc ? b1   : b0;
    const float* gq  = enc ? g_q1 : g_q0;
    const float* gp  = enc ? g_p1 : g_p0;
    const float* att = enc ? attn1 : attn0;

    __syncthreads();
    #pragma unroll
    for (int j = 0; j < 8; j++){
      int idx = t + 256*j;
      int e = idx >> 4, c4 = (idx & 15) * 4;
      *(float4*)&As[e][c4] = *(const float4*)&ef[(size_t)(ebase+e)*64 + c4];
    }
    #pragma unroll
    for (int j = 0; j < 4; j++){
      int idx = t + 256*j;
      int r = idx >> 4, c4 = (idx & 15) * 4;
      *(float4*)&Ws[r][c4] = *(const float4*)&Wx[r*64 + c4];
    }
    __syncthreads();

    float acc[4][8] = {};
    gemm4x8(As, Ws, er, c0, acc);

    float bv[8];
    *(float4*)&bv[0] = *(const float4*)&bb[c0];
    *(float4*)&bv[4] = *(const float4*)&bb[c0+4];

    __syncthreads();
    #pragma unroll
    for (int i = 0; i < 4; i++){
      int sidx = s_src[er+i];
      float4 qa = *(const float4*)&gq[(size_t)sidx*64 + c0];
      float4 qb = *(const float4*)&gq[(size_t)sidx*64 + c0 + 4];
      float h2[8];
      h2[0]=ftanh(acc[i][0]+qa.x+bv[0]); h2[1]=ftanh(acc[i][1]+qa.y+bv[1]);
      h2[2]=ftanh(acc[i][2]+qa.z+bv[2]); h2[3]=ftanh(acc[i][3]+qa.w+bv[3]);
      h2[4]=ftanh(acc[i][4]+qb.x+bv[4]); h2[5]=ftanh(acc[i][5]+qb.y+bv[5]);
      h2[6]=ftanh(acc[i][6]+qb.z+bv[6]); h2[7]=ftanh(acc[i][7]+qb.w+bv[7]);
      *(float4*)&As[er+i][c0]   = make_float4(h2[0],h2[1],h2[2],h2[3]);
      *(float4*)&As[er+i][c0+4] = make_float4(h2[4],h2[5],h2[6],h2[7]);
    }
    #pragma unroll
    for (int j = 0; j < 4; j++){
      int idx = t + 256*j;
      int r = idx >> 4, c4 = (idx & 15) * 4;
      *(float4*)&Ws[r][c4] = *(const float4*)&Wh[r*64 + c4];
    }
    __syncthreads();

    float acc2[4][8] = {};
    gemm4x8(As, Ws, er, c0, acc2);

    float av[8];
    *(float4*)&av[0] = *(const float4*)&att[c0];
    *(float4*)&av[4] = *(const float4*)&att[c0+4];

    #pragma unroll
    for (int i = 0; i < 4; i++){
      int didx = s_dst[er+i];
      float4 pa = *(const float4*)&gp[(size_t)didx*64 + c0];
      float4 pb = *(const float4*)&gp[(size_t)didx*64 + c0 + 4];
      float h3[8];
      h3[0]=ftanh(acc2[i][0]+pa.x+bv[0]); h3[1]=ftanh(acc2[i][1]+pa.y+bv[1]);
      h3[2]=ftanh(acc2[i][2]+pa.z+bv[2]); h3[3]=ftanh(acc2[i][3]+pa.w+bv[3]);
      h3[4]=ftanh(acc2[i][4]+pb.x+bv[4]); h3[5]=ftanh(acc2[i][5]+pb.y+bv[5]);
      h3[6]=ftanh(acc2[i][6]+pb.z+bv[6]); h3[7]=ftanh(acc2[i][7]+pb.w+bv[7]);
      if (enc == 0){
        size_t gb = (size_t)(ebase + er + i) * 64;
        *(float4*)&g_h3[gb + c0]   = make_float4(h3[0],h3[1],h3[2],h3[3]);
        *(float4*)&g_h3[gb + c0+4] = make_float4(h3[4],h3[5],h3[6],h3[7]);
      }
      float pr = h3[0]*av[0]+h3[1]*av[1]+h3[2]*av[2]+h3[3]*av[3]
               + h3[4]*av[4]+h3[5]*av[5]+h3[6]*av[6]+h3[7]*av[7];
      pr += __shfl_xor_sync(0xffffffffu, pr, 1);
      pr += __shfl_xor_sync(0xffffffffu, pr, 2);
      edot[enc][i] = pr;
    }
  }

  if ((cg & 3) == 0){
    float se0 = fsigm(eta0[head]);
    float se1 = fsigm(eta1[head]);
    float gg  = fsigm(delta[head]);
    #pragma unroll
    for (int i = 0; i < 4; i++){
      float sc = (1.0f - gg) * ftanh(se0 * edot[0][i]) + gg * ftanh(se1 * edot[1][i]);
      int e = ebase + er + i;
      g_s[e*2 + head] = sc;
      if (head == 0) atomicAdd(&g_count[s_dst[er+i]], 1);
    }
  }
}

__global__ void k_scan(){
  __shared__ int smv[1024];
  __shared__ int carry_s;
  int t = threadIdx.x;
  if (t == 0) carry_s = 0;
  __syncthreads();
  for (int c = 0; c < NN; c += 1024){
    int i = c + t;
    int v = (i < NN) ? g_count[i] : 0;
    smv[t] = v;
    __syncthreads();
    for (int off = 1; off < 1024; off <<= 1){
      int add = (t >= off) ? smv[t-off] : 0;
      __syncthreads();
      smv[t] += add;
      __syncthreads();
    }
    int carry = carry_s;
    int excl = smv[t] - v + carry;
    if (i < NN){ g_off[i] = excl; g_cursor[i] = excl; }
    int total = smv[1023];
    __syncthreads();
    if (t == 0) carry_s = carry + total;
    __syncthreads();
  }
}

__global__ void k_scatter(const int* __restrict__ dst){
  int e = blockIdx.x*256 + threadIdx.x;
  if (e < NE){
    int d = dst[e];
    int pos = atomicAdd(&g_cursor[d], 1);
    g_perm[pos] = e;
  }
}

__global__ void __launch_bounds__(256) k_agg(const int* __restrict__ src,
                                             const int* __restrict__ prob,
                                             float* __restrict__ out_mm,
                                             float* __restrict__ out_ms){
  int warp = (blockIdx.x * blockDim.x + threadIdx.x) >> 5;
  int lane = threadIdx.x & 31;
  if (warp >= NN) return;
  int node = warp;
  int cnt  = g_count[node];
  int base = g_off[node];

  float mx0 = -3.4e38f, mx1 = -3.4e38f;
  for (int i0 = 0; i0 < cnt; i0 += 32){
    int ii = i0 + lane;
    if (ii < cnt){
      int e = g_perm[base + ii];
      float s0 = g_s[e*2], s1 = g_s[e*2+1];
      mx0 = fmaxf(mx0, s0); mx1 = fmaxf(mx1, s1);
    }
  }
  #pragma unroll
  for (int o = 16; o > 0; o >>= 1){
    mx0 = fmaxf(mx0, __shfl_xor_sync(0xffffffffu, mx0, o));
    mx1 = fmaxf(mx1, __shfl_xor_sync(0xffffffffu, mx1, o));
  }

  float d0=0.f, d1=0.f, msum=0.f, mcnt=0.f, ssum=0.f, scnt=0.f;
  for (int i0 = 0; i0 < cnt; i0 += 32){
    int ii = i0 + lane;
    if (ii < cnt){
      int e = g_perm[base + ii];
      float s0 = g_s[e*2], s1 = g_s[e*2+1];
      d0 += __expf(s0 - mx0);
      d1 += __expf(s1 - mx1);
      float sc = 0.5f * (s0 + s1);
      int p = prob[e];
      if (p > 1){ msum += sc; mcnt += 1.f; }
      else if (p == 1){ ssum += sc; scnt += 1.f; }
    }
  }
  #pragma unroll
  for (int o = 16; o > 0; o >>= 1){
    d0   += __shfl_xor_sync(0xffffffffu, d0, o);
    d1   += __shfl_xor_sync(0xffffffffu, d1, o);
    msum += __shfl_xor_sync(0xffffffffu, msum, o);
    mcnt += __shfl_xor_sync(0xffffffffu, mcnt, o);
    ssum += __shfl_xor_sync(0xffffffffu, ssum, o);
    scnt += __shfl_xor_sync(0xffffffffu, scnt, o);
  }
  float inv0 = __fdividef(1.f, fmaxf(d0, 1e-9f));
  float inv1 = __fdividef(1.f, fmaxf(d1, 1e-9f));

  int head = lane >> 4;
  float mxh  = head ? mx1 : mx0;
  float invh = head ? inv1 : inv0;

  float fx=0.f, fy=0.f, f2x=0.f, f2y=0.f;
  for (int i0 = 0; i0 < cnt; i0 += 32){
    int el = 0;
    if (i0 + lane < cnt) el = g_perm[base + i0 + lane];
    int lim = min(32, cnt - i0);
    for (int j = 0; j < lim; j++){
      int e = __shfl_sync(0xffffffffu, el, j);
      float sh = g_s[e*2 + head];
      float a  = __expf(sh - mxh) * invh;
      int se = src[e];
      float2 hu  = *(const float2*)&g_h [(size_t)se*64 + 2*lane];
      float2 h3v = *(const float2*)&g_h3[(size_t)e *64 + 2*lane];
      fx  += hu.x  * a; fy  += hu.y  * a;
      f2x += h3v.x * a; f2y += h3v.y * a;
    }
  }
  *(float2*)&g_ft [(size_t)node*64 + 2*lane] = make_float2(fx, fy);
  *(float2*)&g_ft2[(size_t)node*64 + 2*lane] = make_float2(f2x, f2y);

  if (lane == 0){
    float ind = (mcnt > 0.f && scnt > 0.f) ? 1.f : 0.f;
    float mm = msum / (mcnt > 0.f ? mcnt : 1.f);
    float ms = ssum / (scnt > 0.f ? scnt : 1.f);
    out_mm[node] = mm * ind;
    out_ms[node] = ms * ind;
  }
}

__global__ void __launch_bounds__(256) k_out(const float* __restrict__ Wsrc, const float* __restrict__ bsrc,
                                             const float* __restrict__ Wedge, const float* __restrict__ bedge,
                                             float* __restrict__ out){
  __shared__ float fts [64][68];
  __shared__ float ft2s[64][68];
  __shared__ float Ws[32][36];
  __shared__ float We[32][36];
  int t = threadIdx.x;
  int r0 = blockIdx.x * 64;
  #pragma unroll
  for (int j = 0; j < 4; j++){
    int idx = t + 256*j;
    int r = idx >> 4, c4 = (idx & 15) * 4;
    float4 v1 = make_float4(0.f,0.f,0.f,0.f), v2 = v1;
    if (r0 + r < NN){
      v1 = *(const float4*)&g_ft [(size_t)(r0+r)*64 + c4];
      v2 = *(const float4*)&g_ft2[(size_t)(r0+r)*64 + c4];
    }
    *(float4*)&fts [r][c4] = v1;
    *(float4*)&ft2s[r][c4] = v2;
  }
  {
    int r = t >> 3, c4 = (t & 7) * 4;
    *(float4*)&Ws[r][c4] = *(const float4*)&Wsrc [r*32 + c4];
    *(float4*)&We[r][c4] = *(const float4*)&Wedge[r*32 + c4];
  }
  __syncthreads();

  int cg = t & 7, eg = t >> 3;
  int c0 = cg * 8, rr = eg * 2;
  int hd = c0 >> 5, dl = c0 & 31;
  float acc[2][8] = {};
  #pragma unroll
  for (int k = 0; k < 32; k++){
    float a0 = fts [rr  ][hd*32 + k], a1 = fts [rr+1][hd*32 + k];
    float c0v= ft2s[rr  ][hd*32 + k], c1v= ft2s[rr+1][hd*32 + k];
    float4 w0 = *(const float4*)&Ws[k][dl];
    float4 w1 = *(const float4*)&Ws[k][dl+4];
    ROW_FMA8(acc[0], a0);
    ROW_FMA8(acc[1], a1);
    w0 = *(const float4*)&We[k][dl];
    w1 = *(const float4*)&We[k][dl+4];
    ROW_FMA8(acc[0], c0v);
    ROW_FMA8(acc[1], c1v);
  }
  float bs[8], be[8];
  *(float4*)&bs[0] = *(const float4*)&bsrc [dl];
  *(float4*)&bs[4] = *(const float4*)&bsrc [dl+4];
  *(float4*)&be[0] = *(const float4*)&bedge[dl];
  *(float4*)&be[4] = *(const float4*)&bedge[dl+4];
  #pragma unroll
  for (int i = 0; i < 2; i++){
    int r = r0 + rr + i;
    if (r < NN){
      float4 h0 = *(const float4*)&g_h[(size_t)r*64 + c0];
      float4 h1 = *(const float4*)&g_h[(size_t)r*64 + c0+4];
      float o[8];
      o[0]=acc[i][0]+bs[0]+be[0]+h0.x; o[1]=acc[i][1]+bs[1]+be[1]+h0.y;
      o[2]=acc[i][2]+bs[2]+be[2]+h0.z; o[3]=acc[i][3]+bs[3]+be[3]+h0.w;
      o[4]=acc[i][4]+bs[4]+be[4]+h1.x; o[5]=acc[i][5]+bs[5]+be[5]+h1.y;
      o[6]=acc[i][6]+bs[6]+be[6]+h1.z; o[7]=acc[i][7]+bs[7]+be[7]+h1.w;
      #pragma unroll
      for (int j = 0; j < 8; j++) o[j] = fmaxf(o[j], 0.f);
      *(float4*)&out[(size_t)r*64 + c0]   = *(float4*)&o[0];
      *(float4*)&out[(size_t)r*64 + c0+4] = *(float4*)&o[4];
    }
  }
}

extern "C" void kernel_launch(void* const* d_in, const int* in_sizes, int n_in,
                              void* d_out, int out_size){
  const float* x     = (const float*)d_in[0];
  const float* ef0   = (const float*)d_in[1];
  const float* ef1   = (const float*)d_in[2];
  const int*   src   = (const int*)  d_in[3];
  const int*   dst   = (const int*)  d_in[4];
  const int*   prob  = (const int*)  d_in[5];
  const float* W_lin = (const float*)d_in[6];
  const float* b_lin = (const float*)d_in[7];
  const float* Wx0   = (const float*)d_in[8];
  const float* Wh0   = (const float*)d_in[9];
  const float* b0    = (const float*)d_in[10];
  const float* Wx1   = (const float*)d_in[11];
  const float* Wh1   = (const float*)d_in[12];
  const float* b1    = (const float*)d_in[13];
  const float* attn0 = (const float*)d_in[14];
  const float* eta0  = (const float*)d_in[15];
  const float* attn1 = (const float*)d_in[16];
  const float* eta1  = (const float*)d_in[17];
  const float* delta = (const float*)d_in[18];
  const float* Wsrc  = (const float*)d_in[19];
  const float* bsrc  = (const float*)d_in[20];
  const float* Wedge = (const float*)d_in[21];
  const float* bedge = (const float*)d_in[22];

  float* out    = (float*)d_out;
  float* out_mm = out + (size_t)NN*64;
  float* out_ms = out_mm + NN;

  const int EDGE_SMEM = (128*68 + 64*68) * (int)sizeof(float) + 256 * (int)sizeof(int);
  const int PQ_SMEM   = 3 * 64 * 68 * (int)sizeof(float);
  cudaFuncSetAttribute(k_edge1,   cudaFuncAttributeMaxDynamicSharedMemorySize, EDGE_SMEM);
  cudaFuncSetAttribute(k_node_pq, cudaFuncAttributeMaxDynamicSharedMemorySize, PQ_SMEM);

  k_zero<<<(NN+255)/256, 256>>>();
  k_node_h<<<(NN+63)/64, 256>>>(x, W_lin, b_lin);
  k_node_pq<<<(NN+63)/64, 256, PQ_SMEM>>>(Wx0, Wh0, b0, Wx1, Wh1, b1);
  k_edge1<<<NE/128, 256, EDGE_SMEM>>>(ef0, ef1, src, dst,
      Wx0, Wh0, b0, Wx1, Wh1, b1, attn0, eta0, attn1, eta1, delta);
  k_scan<<<1, 1024>>>();
  k_scatter<<<(NE+255)/256, 256>>>(dst);
  k_agg<<<(NN*32+255)/256, 256>>>(src, prob, out_mm, out_ms);
  k_out<<<(NN+63)/64, 256>>>(Wsrc, bsrc, Wedge, bedge, out);
}